// round 1
// baseline (speedup 1.0000x reference)
#include <cuda_runtime.h>
#include <math.h>

#define BB 4
#define TT 2048
#define CC 1024
#define HH 16
#define DD 64
#define MM (BB*TT)      // 8192 rows

// Scratch: [B,H,T,D] for q,k,v; [B,T,C] for attention output y.
__device__ float g_q[(size_t)BB*HH*TT*DD];
__device__ float g_k[(size_t)BB*HH*TT*DD];
__device__ float g_v[(size_t)BB*HH*TT*DD];
__device__ float g_y[(size_t)MM*CC];

// ---------------------------------------------------------------------------
// GEMM 1: QKV = X[M,C] @ W[C,3C] + bias, scattered to q/k/v in [B,H,T,D].
// Classic 128x128x8 SGEMM, 256 threads, 8x8 micro-tile, register prefetch.
// ---------------------------------------------------------------------------
__global__ __launch_bounds__(256)
void qkv_kernel(const float* __restrict__ X, const float* __restrict__ W,
                const float* __restrict__ bias)
{
    const int N = 3 * CC;
    __shared__ float As[8][128];   // transposed A tile: As[k][m]
    __shared__ float Bs[8][128];   // Bs[k][n]

    const int t  = threadIdx.x;
    const int ty = t >> 4, tx = t & 15;
    const int bm = blockIdx.y, bn = blockIdx.x;

    const float* Aptr = X + (size_t)(bm * 128 + (t >> 1)) * CC + (t & 1) * 4;
    const float* Bptr = W + (size_t)(t >> 5) * N + bn * 128 + (t & 31) * 4;

    float4 aReg = *(const float4*)Aptr;
    float4 bReg = *(const float4*)Bptr;

    float acc[8][8];
#pragma unroll
    for (int i = 0; i < 8; i++)
#pragma unroll
        for (int j = 0; j < 8; j++) acc[i][j] = 0.f;

    const int KT = CC / 8;
#pragma unroll 1
    for (int kt = 0; kt < KT; ++kt) {
        As[(t & 1) * 4 + 0][t >> 1] = aReg.x;
        As[(t & 1) * 4 + 1][t >> 1] = aReg.y;
        As[(t & 1) * 4 + 2][t >> 1] = aReg.z;
        As[(t & 1) * 4 + 3][t >> 1] = aReg.w;
        *(float4*)&Bs[t >> 5][(t & 31) * 4] = bReg;
        __syncthreads();
        if (kt + 1 < KT) {
            aReg = *(const float4*)(Aptr + (size_t)(kt + 1) * 8);
            bReg = *(const float4*)(Bptr + (size_t)(kt + 1) * 8 * N);
        }
#pragma unroll
        for (int k = 0; k < 8; ++k) {
            float4 a0 = *(const float4*)&As[k][ty * 8];
            float4 a1 = *(const float4*)&As[k][ty * 8 + 4];
            float4 b0 = *(const float4*)&Bs[k][tx * 8];
            float4 b1 = *(const float4*)&Bs[k][tx * 8 + 4];
            float av[8] = {a0.x, a0.y, a0.z, a0.w, a1.x, a1.y, a1.z, a1.w};
            float bv[8] = {b0.x, b0.y, b0.z, b0.w, b1.x, b1.y, b1.z, b1.w};
#pragma unroll
            for (int i = 0; i < 8; i++)
#pragma unroll
                for (int j = 0; j < 8; j++)
                    acc[i][j] += av[i] * bv[j];
        }
        __syncthreads();
    }

    // Epilogue: add bias, scatter to q/k/v as [B,H,T,D].
#pragma unroll
    for (int i = 0; i < 8; i++) {
        const int row = bm * 128 + ty * 8 + i;
        const int b   = row >> 11;        // / TT
        const int tt  = row & (TT - 1);
#pragma unroll
        for (int j = 0; j < 8; j++) {
            const int col = bn * 128 + tx * 8 + j;
            const float val = acc[i][j] + bias[col];
            const int sel = col >> 10;        // 0=q 1=k 2=v
            const int c   = col & (CC - 1);
            const int h   = c >> 6;
            const int d   = c & 63;
            float* dst = (sel == 0) ? g_q : (sel == 1) ? g_k : g_v;
            dst[((size_t)(b * HH + h) * TT + tt) * DD + d] = val;
        }
    }
}

// ---------------------------------------------------------------------------
// GEMM 2: out = y[M,C] @ Wp[C,C] + bias. Same SGEMM, plain epilogue.
// ---------------------------------------------------------------------------
__global__ __launch_bounds__(256)
void proj_kernel(const float* __restrict__ W, const float* __restrict__ bias,
                 float* __restrict__ out)
{
    const int N = CC;
    __shared__ float As[8][128];
    __shared__ float Bs[8][128];

    const int t  = threadIdx.x;
    const int ty = t >> 4, tx = t & 15;
    const int bm = blockIdx.y, bn = blockIdx.x;

    const float* Aptr = g_y + (size_t)(bm * 128 + (t >> 1)) * CC + (t & 1) * 4;
    const float* Bptr = W + (size_t)(t >> 5) * N + bn * 128 + (t & 31) * 4;

    float4 aReg = *(const float4*)Aptr;
    float4 bReg = *(const float4*)Bptr;

    float acc[8][8];
#pragma unroll
    for (int i = 0; i < 8; i++)
#pragma unroll
        for (int j = 0; j < 8; j++) acc[i][j] = 0.f;

    const int KT = CC / 8;
#pragma unroll 1
    for (int kt = 0; kt < KT; ++kt) {
        As[(t & 1) * 4 + 0][t >> 1] = aReg.x;
        As[(t & 1) * 4 + 1][t >> 1] = aReg.y;
        As[(t & 1) * 4 + 2][t >> 1] = aReg.z;
        As[(t & 1) * 4 + 3][t >> 1] = aReg.w;
        *(float4*)&Bs[t >> 5][(t & 31) * 4] = bReg;
        __syncthreads();
        if (kt + 1 < KT) {
            aReg = *(const float4*)(Aptr + (size_t)(kt + 1) * 8);
            bReg = *(const float4*)(Bptr + (size_t)(kt + 1) * 8 * N);
        }
#pragma unroll
        for (int k = 0; k < 8; ++k) {
            float4 a0 = *(const float4*)&As[k][ty * 8];
            float4 a1 = *(const float4*)&As[k][ty * 8 + 4];
            float4 b0 = *(const float4*)&Bs[k][tx * 8];
            float4 b1 = *(const float4*)&Bs[k][tx * 8 + 4];
            float av[8] = {a0.x, a0.y, a0.z, a0.w, a1.x, a1.y, a1.z, a1.w};
            float bv[8] = {b0.x, b0.y, b0.z, b0.w, b1.x, b1.y, b1.z, b1.w};
#pragma unroll
            for (int i = 0; i < 8; i++)
#pragma unroll
                for (int j = 0; j < 8; j++)
                    acc[i][j] += av[i] * bv[j];
        }
        __syncthreads();
    }

#pragma unroll
    for (int i = 0; i < 8; i++) {
        const int row = bm * 128 + ty * 8 + i;
#pragma unroll
        for (int j = 0; j < 8; j++) {
            const int col = bn * 128 + tx * 8 + j;
            out[(size_t)row * CC + col] = acc[i][j] + bias[col];
        }
    }
}

// ---------------------------------------------------------------------------
// Flash attention, fp32, causal. One block per (q-tile of 64, head, batch).
// 256 threads as 16x16; each thread owns a 4x4 micro-tile of S/P and of O.
// Online softmax with running (m, l). ~66.5 KB dynamic shared.
// ---------------------------------------------------------------------------
__global__ __launch_bounds__(256)
void attn_kernel()
{
    extern __shared__ float sm[];
    float* Qs = sm;                 // [64][65]
    float* Ks = Qs + 64 * 65;       // [64][65]
    float* Vs = Ks + 64 * 65;       // [64][65]
    float* Ps = Vs + 64 * 65;       // [64][65]

    const int qt = blockIdx.x, h = blockIdx.y, b = blockIdx.z;
    const int t  = threadIdx.x;
    const int ty = t >> 4, tx = t & 15;

    const size_t bh = ((size_t)b * HH + h) * TT * DD;
    const float* qb = g_q + bh;
    const float* kb = g_k + bh;
    const float* vb = g_v + bh;

    // Load Q tile (coalesced)
    for (int idx = t; idx < 64 * 64; idx += 256) {
        const int r = idx >> 6, c = idx & 63;
        Qs[r * 65 + c] = qb[(size_t)(qt * 64 + r) * DD + c];
    }

    float m[4], l[4], o[4][4];
#pragma unroll
    for (int i = 0; i < 4; i++) {
        m[i] = -1e30f; l[i] = 0.f;
#pragma unroll
        for (int j = 0; j < 4; j++) o[i][j] = 0.f;
    }
    const float scale = 0.125f;     // 1/sqrt(64)

#pragma unroll 1
    for (int kt = 0; kt <= qt; ++kt) {
        __syncthreads();            // protect Ks/Vs (prev PV) and Q first iter
        for (int idx = t; idx < 64 * 64; idx += 256) {
            const int r = idx >> 6, c = idx & 63;
            Ks[r * 65 + c] = kb[(size_t)(kt * 64 + r) * DD + c];
            Vs[r * 65 + c] = vb[(size_t)(kt * 64 + r) * DD + c];
        }
        __syncthreads();

        // S = Q K^T  (4x4 per thread)
        float s[4][4];
#pragma unroll
        for (int i = 0; i < 4; i++)
#pragma unroll
            for (int j = 0; j < 4; j++) s[i][j] = 0.f;

#pragma unroll 8
        for (int kd = 0; kd < 64; ++kd) {
            float a[4], bb4[4];
#pragma unroll
            for (int i = 0; i < 4; i++) a[i]   = Qs[(ty * 4 + i) * 65 + kd];
#pragma unroll
            for (int j = 0; j < 4; j++) bb4[j] = Ks[(tx * 4 + j) * 65 + kd];
#pragma unroll
            for (int i = 0; i < 4; i++)
#pragma unroll
                for (int j = 0; j < 4; j++)
                    s[i][j] += a[i] * bb4[j];
        }

        // scale + causal mask (only the diagonal tile needs masking)
        const bool diag = (kt == qt);
#pragma unroll
        for (int i = 0; i < 4; i++)
#pragma unroll
            for (int j = 0; j < 4; j++) {
                float v = s[i][j] * scale;
                if (diag && (tx * 4 + j) > (ty * 4 + i)) v = -1e30f;
                s[i][j] = v;
            }

        // Online softmax update. Row groups are half-warps (same ty), so
        // width-16 shfl butterflies reduce across the 16 tx lanes.
#pragma unroll
        for (int i = 0; i < 4; i++) {
            float rm = fmaxf(fmaxf(s[i][0], s[i][1]), fmaxf(s[i][2], s[i][3]));
#pragma unroll
            for (int off = 8; off > 0; off >>= 1)
                rm = fmaxf(rm, __shfl_xor_sync(0xffffffffu, rm, off, 16));
            const float mn   = fmaxf(m[i], rm);
            const float corr = __expf(m[i] - mn);
            m[i] = mn;
            float rs = 0.f;
#pragma unroll
            for (int j = 0; j < 4; j++) {
                const float p = __expf(s[i][j] - mn);
                s[i][j] = p;
                rs += p;
            }
#pragma unroll
            for (int off = 8; off > 0; off >>= 1)
                rs += __shfl_xor_sync(0xffffffffu, rs, off, 16);
            l[i] = l[i] * corr + rs;
#pragma unroll
            for (int j = 0; j < 4; j++) o[i][j] *= corr;
        }

        // P to shared for the PV GEMM
#pragma unroll
        for (int i = 0; i < 4; i++)
#pragma unroll
            for (int j = 0; j < 4; j++)
                Ps[(ty * 4 + i) * 65 + tx * 4 + j] = s[i][j];
        __syncthreads();

        // O += P V   (thread owns rows ty*4.., d-cols tx*4..)
#pragma unroll 8
        for (int kc = 0; kc < 64; ++kc) {
            float pa[4], vv[4];
#pragma unroll
            for (int i = 0; i < 4; i++) pa[i] = Ps[(ty * 4 + i) * 65 + kc];
#pragma unroll
            for (int j = 0; j < 4; j++) vv[j] = Vs[kc * 65 + tx * 4 + j];
#pragma unroll
            for (int i = 0; i < 4; i++)
#pragma unroll
                for (int j = 0; j < 4; j++)
                    o[i][j] += pa[i] * vv[j];
        }
    }

    // Epilogue: y[B,T,C] with c = h*64 + d
#pragma unroll
    for (int i = 0; i < 4; i++) {
        const int qg  = qt * 64 + ty * 4 + i;
        const float inv = 1.f / l[i];
#pragma unroll
        for (int j = 0; j < 4; j++) {
            const int dj = tx * 4 + j;
            g_y[(size_t)(b * TT + qg) * CC + h * DD + dj] = o[i][j] * inv;
        }
    }
}

// ---------------------------------------------------------------------------
extern "C" void kernel_launch(void* const* d_in, const int* in_sizes, int n_in,
                              void* d_out, int out_size)
{
    const float* x      = (const float*)d_in[0];
    const float* w_attn = (const float*)d_in[1];
    const float* b_attn = (const float*)d_in[2];
    const float* w_proj = (const float*)d_in[3];
    const float* b_proj = (const float*)d_in[4];
    float* out = (float*)d_out;

    const int attn_smem = 4 * 64 * 65 * (int)sizeof(float);   // 66560 B
    cudaFuncSetAttribute(attn_kernel,
                         cudaFuncAttributeMaxDynamicSharedMemorySize, attn_smem);

    dim3 g1(3 * CC / 128, MM / 128);      // 24 x 64
    qkv_kernel<<<g1, 256>>>(x, w_attn, b_attn);

    dim3 g2(TT / 64, HH, BB);             // 32 x 16 x 4
    attn_kernel<<<g2, 256, attn_smem>>>();

    dim3 g3(CC / 128, MM / 128);          // 8 x 64
    proj_kernel<<<g3, 256>>>(w_proj, b_proj, out);
}

// round 12
// speedup vs baseline: 1.5387x; 1.5387x over previous
#include <cuda_runtime.h>
#include <cuda_bf16.h>
#include <cstdint>
#include <math.h>

#define BB 4
#define TT 2048
#define CC 1024
#define HH 16
#define DD 64
#define MM (BB*TT)          // 8192
#define NQKV (3*CC)         // 3072

// ---------------- scratch (device globals; no allocs allowed) --------------
__device__ float g_q[(size_t)BB*HH*TT*DD];
__device__ float g_k[(size_t)BB*HH*TT*DD];
__device__ float g_v[(size_t)BB*HH*TT*DD];
__device__ __nv_bfloat16 g_xhi[(size_t)MM*CC],  g_xlo[(size_t)MM*CC];
__device__ __nv_bfloat16 g_wahi[(size_t)NQKV*CC], g_walo[(size_t)NQKV*CC]; // [N][K] K-major
__device__ __nv_bfloat16 g_wphi[(size_t)CC*CC],   g_wplo[(size_t)CC*CC];   // [N][K]
__device__ __nv_bfloat16 g_yhi[(size_t)MM*CC],  g_ylo[(size_t)MM*CC];

__device__ __forceinline__ uint32_t smem_u32(const void* p) {
    uint32_t a;
    asm("{ .reg .u64 t; cvta.to.shared.u64 t, %1; cvt.u32.u64 %0, t; }" : "=r"(a) : "l"(p));
    return a;
}

// ldmatrix x4 (non-trans) -- base PTX, sm_75+
#define LDSM4(r0, r1, r2, r3, addr) \
    asm volatile("ldmatrix.sync.aligned.m8n8.x4.shared.b16 {%0,%1,%2,%3}, [%4];" \
        : "=r"(r0), "=r"(r1), "=r"(r2), "=r"(r3) : "r"(addr))

// mma m16n8k16 bf16 -> f32 -- base PTX, sm_80+
#define MMA16816(d, a0, a1, a2, a3, b0, b1) \
    asm volatile("mma.sync.aligned.m16n8k16.row.col.f32.bf16.bf16.f32 " \
        "{%0,%1,%2,%3}, {%4,%5,%6,%7}, {%8,%9}, {%0,%1,%2,%3};" \
        : "+f"((d)[0]), "+f"((d)[1]), "+f"((d)[2]), "+f"((d)[3]) \
        : "r"(a0), "r"(a1), "r"(a2), "r"(a3), "r"(b0), "r"(b1))

// ---------------- prep kernels ---------------------------------------------
__global__ __launch_bounds__(256)
void split_x_kernel(const float* __restrict__ x)
{
    const int idx = blockIdx.x * 256 + threadIdx.x;          // 1 float4 each
    if ((size_t)idx * 4 >= (size_t)MM * CC) return;
    const float4 v = ((const float4*)x)[idx];
    __nv_bfloat162 h01, h23, l01, l23;
    h01.x = __float2bfloat16(v.x); h01.y = __float2bfloat16(v.y);
    h23.x = __float2bfloat16(v.z); h23.y = __float2bfloat16(v.w);
    l01.x = __float2bfloat16(v.x - __bfloat162float(h01.x));
    l01.y = __float2bfloat16(v.y - __bfloat162float(h01.y));
    l23.x = __float2bfloat16(v.z - __bfloat162float(h23.x));
    l23.y = __float2bfloat16(v.w - __bfloat162float(h23.y));
    ((__nv_bfloat162*)g_xhi)[idx * 2]     = h01;
    ((__nv_bfloat162*)g_xhi)[idx * 2 + 1] = h23;
    ((__nv_bfloat162*)g_xlo)[idx * 2]     = l01;
    ((__nv_bfloat162*)g_xlo)[idx * 2 + 1] = l23;
}

// W [K=1024, N] row-major -> Thi/Tlo [N][K] bf16 (transpose + split)
__global__ __launch_bounds__(256)
void transpose_split_kernel(const float* __restrict__ W,
                            __nv_bfloat16* __restrict__ Thi,
                            __nv_bfloat16* __restrict__ Tlo, int N)
{
    __shared__ float tile[32][33];
    const int tx = threadIdx.x, ty = threadIdx.y;            // 32 x 8
    const int nbase = blockIdx.x * 32, kbase = blockIdx.y * 32;
#pragma unroll
    for (int i = 0; i < 4; i++)
        tile[ty + i * 8][tx] = W[(size_t)(kbase + ty + i * 8) * N + nbase + tx];
    __syncthreads();
#pragma unroll
    for (int i = 0; i < 4; i++) {
        const int n = nbase + ty + i * 8;
        const int k = kbase + tx;
        const float v = tile[tx][ty + i * 8];
        const __nv_bfloat16 h = __float2bfloat16(v);
        Thi[(size_t)n * CC + k] = h;
        Tlo[(size_t)n * CC + k] = __float2bfloat16(v - __bfloat162float(h));
    }
}

// ---------------- mma.sync bf16x3 GEMM -------------------------------------
// C[M,N] = Ahi@Bhi^T + Ahi@Blo^T + Alo@Bhi^T (+bias). A [M][K], B [N][K] K-major.
// Block tile 128x64, 8 warps (4m x 2n), warp tile 32x32, K chunks of 64.
// SMEM rows padded to 72 halves (144B) -> conflict-free ldmatrix.
// EPI==0: bias + scatter to g_q/g_k/g_v.  EPI==1: out + bias.
#define SROW 72
template<int EPI>
__global__ __launch_bounds__(256)
void gemm_mma_bf16x3(const __nv_bfloat16* __restrict__ Ahi, const __nv_bfloat16* __restrict__ Alo,
                     const __nv_bfloat16* __restrict__ Bhi, const __nv_bfloat16* __restrict__ Blo,
                     const float* __restrict__ bias, float* __restrict__ out)
{
    extern __shared__ __nv_bfloat16 smem[];   // 384 rows x 72 halves
    const uint32_t sb = smem_u32(smem);
    const int tid = threadIdx.x;
    const int lane = tid & 31, w = tid >> 5;
    const int wm = w & 3, wn = w >> 1 >> 1;    // wm 0..3, wn 0..1  (w>>2)
    const int bn = blockIdx.x, bm = blockIdx.y;

    // ldmatrix per-lane offsets
    const int q4   = lane >> 3;
    const int rowA = (lane & 7) + (q4 & 1) * 8;
    const int kA   = (q4 >> 1) * 8;
    const int rowB = (lane & 7) + ((lane >> 4) & 1) * 8;
    const int kB   = ((lane >> 3) & 1) * 8;

    // smem base addresses (bytes) for this warp's fragments
    // rows: Ah 0-127, Al 128-255, Bh 256-319, Bl 320-383 (uniform stride SROW)
    uint32_t aH[2], aL[2], bH[2], bL[2];
#pragma unroll
    for (int mt = 0; mt < 2; ++mt) {
        const int r = wm * 32 + mt * 16 + rowA;
        aH[mt] = sb + 2u * (r * SROW + kA);
        aL[mt] = aH[mt] + 2u * 128 * SROW;
    }
#pragma unroll
    for (int p = 0; p < 2; ++p) {
        const int r = 256 + wn * 32 + p * 16 + rowB;
        bH[p] = sb + 2u * (r * SROW + kB);
        bL[p] = bH[p] + 2u * 64 * SROW;
    }

    float acc[2][4][4];
#pragma unroll
    for (int mt = 0; mt < 2; ++mt)
#pragma unroll
        for (int nt = 0; nt < 4; ++nt)
#pragma unroll
            for (int e = 0; e < 4; ++e) acc[mt][nt][e] = 0.f;

#pragma unroll 1
    for (int ck = 0; ck < 16; ++ck) {
        // ---- load chunk: 384 rows x 64 halves; 3072 uint4, 12 per thread ----
#pragma unroll
        for (int i = 0; i < 12; ++i) {
            const int idx = tid + 256 * i;
            const int r = idx >> 3, cg = idx & 7;
            const __nv_bfloat16* src;
            int grow;
            if (r < 128)      { src = Ahi; grow = bm * 128 + r; }
            else if (r < 256) { src = Alo; grow = bm * 128 + (r - 128); }
            else if (r < 320) { src = Bhi; grow = bn * 64 + (r - 256); }
            else              { src = Blo; grow = bn * 64 + (r - 320); }
            const uint4 v = *(const uint4*)(src + (size_t)grow * CC + ck * 64 + cg * 8);
            *(uint4*)((char*)smem + ((size_t)r * SROW + cg * 8) * 2) = v;
        }
        __syncthreads();

        // ---- compute: 4 k16 steps ----
#pragma unroll
        for (int ks = 0; ks < 4; ++ks) {
            const uint32_t koff = ks * 32;   // 16 halves
            uint32_t ah[2][4], al[2][4], bh[2][4], bl[2][4];
#pragma unroll
            for (int mt = 0; mt < 2; ++mt) {
                LDSM4(ah[mt][0], ah[mt][1], ah[mt][2], ah[mt][3], aH[mt] + koff);
                LDSM4(al[mt][0], al[mt][1], al[mt][2], al[mt][3], aL[mt] + koff);
            }
#pragma unroll
            for (int p = 0; p < 2; ++p) {
                LDSM4(bh[p][0], bh[p][1], bh[p][2], bh[p][3], bH[p] + koff);
                LDSM4(bl[p][0], bl[p][1], bl[p][2], bl[p][3], bL[p] + koff);
            }
#pragma unroll
            for (int mt = 0; mt < 2; ++mt)
#pragma unroll
                for (int p = 0; p < 2; ++p)
#pragma unroll
                    for (int t = 0; t < 2; ++t) {
                        const int nt = p * 2 + t;
                        MMA16816(acc[mt][nt], ah[mt][0], ah[mt][1], ah[mt][2], ah[mt][3],
                                 bh[p][t * 2], bh[p][t * 2 + 1]);
                        MMA16816(acc[mt][nt], ah[mt][0], ah[mt][1], ah[mt][2], ah[mt][3],
                                 bl[p][t * 2], bl[p][t * 2 + 1]);
                        MMA16816(acc[mt][nt], al[mt][0], al[mt][1], al[mt][2], al[mt][3],
                                 bh[p][t * 2], bh[p][t * 2 + 1]);
                    }
        }
        __syncthreads();
    }

    // ---- epilogue ----
    const int g = lane >> 2, tg = lane & 3;
#pragma unroll
    for (int mt = 0; mt < 2; ++mt)
#pragma unroll
        for (int nt = 0; nt < 4; ++nt) {
            const int col = bn * 64 + wn * 32 + nt * 8 + tg * 2;
            const float bi0 = bias[col], bi1 = bias[col + 1];
#pragma unroll
            for (int half = 0; half < 2; ++half) {
                const int row = bm * 128 + wm * 32 + mt * 16 + g + half * 8;
                const float v0 = acc[mt][nt][half * 2]     + bi0;
                const float v1 = acc[mt][nt][half * 2 + 1] + bi1;
                if (EPI == 0) {
                    const int b = row >> 11, tt = row & (TT - 1);
                    const int sel = col >> 10;
                    const int c = col & (CC - 1);
                    const int h = c >> 6, d = c & 63;
                    float* dst = (sel == 0) ? g_q : (sel == 1) ? g_k : g_v;
                    float2* p2 = (float2*)&dst[((size_t)(b * HH + h) * TT + tt) * DD + d];
                    *p2 = make_float2(v0, v1);
                } else {
                    float2* p2 = (float2*)&out[(size_t)row * CC + col];
                    *p2 = make_float2(v0, v1);
                }
            }
        }
}

// ---------------- flash attention (fp32 FMA, unchanged math) ---------------
__global__ __launch_bounds__(256)
void attn_kernel()
{
    extern __shared__ float sm[];
    float* Qs = sm;
    float* Ks = Qs + 64 * 65;
    float* Vs = Ks + 64 * 65;
    float* Ps = Vs + 64 * 65;

    const int qt = blockIdx.x, h = blockIdx.y, b = blockIdx.z;
    const int t  = threadIdx.x;
    const int ty = t >> 4, tx = t & 15;

    const size_t bh = ((size_t)b * HH + h) * TT * DD;
    const float* qb = g_q + bh;
    const float* kb = g_k + bh;
    const float* vb = g_v + bh;

    for (int idx = t; idx < 64 * 64; idx += 256) {
        const int r = idx >> 6, c = idx & 63;
        Qs[r * 65 + c] = qb[(size_t)(qt * 64 + r) * DD + c];
    }

    float m[4], l[4], o[4][4];
#pragma unroll
    for (int i = 0; i < 4; i++) {
        m[i] = -1e30f; l[i] = 0.f;
#pragma unroll
        for (int j = 0; j < 4; j++) o[i][j] = 0.f;
    }
    const float scale = 0.125f;

#pragma unroll 1
    for (int kt = 0; kt <= qt; ++kt) {
        __syncthreads();
        for (int idx = t; idx < 64 * 64; idx += 256) {
            const int r = idx >> 6, c = idx & 63;
            Ks[r * 65 + c] = kb[(size_t)(kt * 64 + r) * DD + c];
            Vs[r * 65 + c] = vb[(size_t)(kt * 64 + r) * DD + c];
        }
        __syncthreads();

        float s[4][4];
#pragma unroll
        for (int i = 0; i < 4; i++)
#pragma unroll
            for (int j = 0; j < 4; j++) s[i][j] = 0.f;

#pragma unroll 8
        for (int kd = 0; kd < 64; ++kd) {
            float a[4], bb4[4];
#pragma unroll
            for (int i = 0; i < 4; i++) a[i]   = Qs[(ty * 4 + i) * 65 + kd];
#pragma unroll
            for (int j = 0; j < 4; j++) bb4[j] = Ks[(tx * 4 + j) * 65 + kd];
#pragma unroll
            for (int i = 0; i < 4; i++)
#pragma unroll
                for (int j = 0; j < 4; j++)
                    s[i][j] += a[i] * bb4[j];
        }

        const bool diag = (kt == qt);
#pragma unroll
        for (int i = 0; i < 4; i++)
#pragma unroll
            for (int j = 0; j < 4; j++) {
                float v = s[i][j] * scale;
                if (diag && (tx * 4 + j) > (ty * 4 + i)) v = -1e30f;
                s[i][j] = v;
            }

#pragma unroll
        for (int i = 0; i < 4; i++) {
            float rm = fmaxf(fmaxf(s[i][0], s[i][1]), fmaxf(s[i][2], s[i][3]));
#pragma unroll
            for (int off = 8; off > 0; off >>= 1)
                rm = fmaxf(rm, __shfl_xor_sync(0xffffffffu, rm, off, 16));
            const float mn   = fmaxf(m[i], rm);
            const float corr = __expf(m[i] - mn);
            m[i] = mn;
            float rs = 0.f;
#pragma unroll
            for (int j = 0; j < 4; j++) {
                const float p = __expf(s[i][j] - mn);
                s[i][j] = p;
                rs += p;
            }
#pragma unroll
            for (int off = 8; off > 0; off >>= 1)
                rs += __shfl_xor_sync(0xffffffffu, rs, off, 16);
            l[i] = l[i] * corr + rs;
#pragma unroll
            for (int j = 0; j < 4; j++) o[i][j] *= corr;
        }

#pragma unroll
        for (int i = 0; i < 4; i++)
#pragma unroll
            for (int j = 0; j < 4; j++)
                Ps[(ty * 4 + i) * 65 + tx * 4 + j] = s[i][j];
        __syncthreads();

#pragma unroll 8
        for (int kc = 0; kc < 64; ++kc) {
            float pa[4], vv[4];
#pragma unroll
            for (int i = 0; i < 4; i++) pa[i] = Ps[(ty * 4 + i) * 65 + kc];
#pragma unroll
            for (int j = 0; j < 4; j++) vv[j] = Vs[kc * 65 + tx * 4 + j];
#pragma unroll
            for (int i = 0; i < 4; i++)
#pragma unroll
                for (int j = 0; j < 4; j++)
                    o[i][j] += pa[i] * vv[j];
        }
    }

    // epilogue: write y as hi/lo bf16 (proj GEMM consumes these directly)
#pragma unroll
    for (int i = 0; i < 4; i++) {
        const int qg  = qt * 64 + ty * 4 + i;
        const float inv = 1.f / l[i];
        const float v0 = o[i][0] * inv, v1 = o[i][1] * inv;
        const float v2 = o[i][2] * inv, v3 = o[i][3] * inv;
        __nv_bfloat162 h01, h23, l01, l23;
        h01.x = __float2bfloat16(v0); h01.y = __float2bfloat16(v1);
        h23.x = __float2bfloat16(v2); h23.y = __float2bfloat16(v3);
        l01.x = __float2bfloat16(v0 - __bfloat162float(h01.x));
        l01.y = __float2bfloat16(v1 - __bfloat162float(h01.y));
        l23.x = __float2bfloat16(v2 - __bfloat162float(h23.x));
        l23.y = __float2bfloat16(v3 - __bfloat162float(h23.y));
        const size_t idx = (size_t)(b * TT + qg) * CC + h * DD + tx * 4;
        *(__nv_bfloat162*)(g_yhi + idx)     = h01;
        *(__nv_bfloat162*)(g_yhi + idx + 2) = h23;
        *(__nv_bfloat162*)(g_ylo + idx)     = l01;
        *(__nv_bfloat162*)(g_ylo + idx + 2) = l23;
    }
}

// ---------------------------------------------------------------------------
extern "C" void kernel_launch(void* const* d_in, const int* in_sizes, int n_in,
                              void* d_out, int out_size)
{
    const float* x      = (const float*)d_in[0];
    const float* w_attn = (const float*)d_in[1];
    const float* b_attn = (const float*)d_in[2];
    const float* w_proj = (const float*)d_in[3];
    const float* b_proj = (const float*)d_in[4];
    float* out = (float*)d_out;

    const int gemm_smem = 384 * SROW * 2;                     // 55296 B
    const int attn_smem = 4 * 64 * 65 * (int)sizeof(float);   // 66560 B
    cudaFuncSetAttribute(gemm_mma_bf16x3<0>, cudaFuncAttributeMaxDynamicSharedMemorySize, gemm_smem);
    cudaFuncSetAttribute(gemm_mma_bf16x3<1>, cudaFuncAttributeMaxDynamicSharedMemorySize, gemm_smem);
    cudaFuncSetAttribute(attn_kernel,        cudaFuncAttributeMaxDynamicSharedMemorySize, attn_smem);

    __nv_bfloat16 *xhi, *xlo, *wahi, *walo, *wphi, *wplo, *yhi, *ylo;
    cudaGetSymbolAddress((void**)&xhi,  g_xhi);
    cudaGetSymbolAddress((void**)&xlo,  g_xlo);
    cudaGetSymbolAddress((void**)&wahi, g_wahi);
    cudaGetSymbolAddress((void**)&walo, g_walo);
    cudaGetSymbolAddress((void**)&wphi, g_wphi);
    cudaGetSymbolAddress((void**)&wplo, g_wplo);
    cudaGetSymbolAddress((void**)&yhi,  g_yhi);
    cudaGetSymbolAddress((void**)&ylo,  g_ylo);

    // prep: split X, transpose+split weights
    split_x_kernel<<<(MM * CC / 4 + 255) / 256, 256>>>(x);
    transpose_split_kernel<<<dim3(NQKV / 32, CC / 32), dim3(32, 8)>>>(w_attn, wahi, walo, NQKV);
    transpose_split_kernel<<<dim3(CC / 32, CC / 32),   dim3(32, 8)>>>(w_proj, wphi, wplo, CC);

    // QKV = X @ W_attn + b  (mma.sync bf16x3) -> scatter to q/k/v
    gemm_mma_bf16x3<0><<<dim3(NQKV / 64, MM / 128), 256, gemm_smem>>>(xhi, xlo, wahi, walo, b_attn, nullptr);

    // attention (fp32 FMA) -> y hi/lo
    attn_kernel<<<dim3(TT / 64, HH, BB), 256, attn_smem>>>();

    // out = y @ W_proj + b  (mma.sync bf16x3)
    gemm_mma_bf16x3<1><<<dim3(CC / 64, MM / 128), 256, gemm_smem>>>(yhi, ylo, wphi, wplo, b_proj, out);
}

// round 13
// speedup vs baseline: 2.7625x; 1.7953x over previous
#include <cuda_runtime.h>
#include <cuda_bf16.h>
#include <cstdint>
#include <math.h>

#define BB 4
#define TT 2048
#define CC 1024
#define HH 16
#define DD 64
#define MM (BB*TT)          // 8192
#define NQKV (3*CC)         // 3072

// ---------------- scratch (device globals; no allocs allowed) --------------
__device__ __nv_bfloat16 g_qhi[(size_t)BB*HH*TT*DD], g_qlo[(size_t)BB*HH*TT*DD];
__device__ __nv_bfloat16 g_khi[(size_t)BB*HH*TT*DD], g_klo[(size_t)BB*HH*TT*DD];
__device__ __nv_bfloat16 g_vhi[(size_t)BB*HH*TT*DD], g_vlo[(size_t)BB*HH*TT*DD];
__device__ __nv_bfloat16 g_xhi[(size_t)MM*CC],  g_xlo[(size_t)MM*CC];
__device__ __nv_bfloat16 g_wahi[(size_t)NQKV*CC], g_walo[(size_t)NQKV*CC]; // [N][K] K-major
__device__ __nv_bfloat16 g_wphi[(size_t)CC*CC],   g_wplo[(size_t)CC*CC];   // [N][K]
__device__ __nv_bfloat16 g_yhi[(size_t)MM*CC],  g_ylo[(size_t)MM*CC];

__device__ __forceinline__ uint32_t smem_u32(const void* p) {
    uint32_t a;
    asm("{ .reg .u64 t; cvta.to.shared.u64 t, %1; cvt.u32.u64 %0, t; }" : "=r"(a) : "l"(p));
    return a;
}

// ldmatrix x4 (non-trans / trans) -- base PTX
#define LDSM4(r0, r1, r2, r3, addr) \
    asm volatile("ldmatrix.sync.aligned.m8n8.x4.shared.b16 {%0,%1,%2,%3}, [%4];" \
        : "=r"(r0), "=r"(r1), "=r"(r2), "=r"(r3) : "r"(addr))
#define LDSM4T(r0, r1, r2, r3, addr) \
    asm volatile("ldmatrix.sync.aligned.m8n8.x4.trans.shared.b16 {%0,%1,%2,%3}, [%4];" \
        : "=r"(r0), "=r"(r1), "=r"(r2), "=r"(r3) : "r"(addr))

// mma m16n8k16 bf16 -> f32 -- base PTX, sm_80+
#define MMA16816(d, a0, a1, a2, a3, b0, b1) \
    asm volatile("mma.sync.aligned.m16n8k16.row.col.f32.bf16.bf16.f32 " \
        "{%0,%1,%2,%3}, {%4,%5,%6,%7}, {%8,%9}, {%0,%1,%2,%3};" \
        : "+f"((d)[0]), "+f"((d)[1]), "+f"((d)[2]), "+f"((d)[3]) \
        : "r"(a0), "r"(a1), "r"(a2), "r"(a3), "r"(b0), "r"(b1))

// split two fp32 into packed bf16x2 hi + bf16x2 lo (elem0 -> low half)
__device__ __forceinline__ void split2(float a, float b, uint32_t& hi, uint32_t& lo) {
    __nv_bfloat16 ha = __float2bfloat16(a), hb = __float2bfloat16(b);
    __nv_bfloat162 H; H.x = ha; H.y = hb;
    __nv_bfloat162 L;
    L.x = __float2bfloat16(a - __bfloat162float(ha));
    L.y = __float2bfloat16(b - __bfloat162float(hb));
    hi = *(uint32_t*)&H; lo = *(uint32_t*)&L;
}

// ---------------- prep kernels ---------------------------------------------
__global__ __launch_bounds__(256)
void split_x_kernel(const float* __restrict__ x)
{
    const int idx = blockIdx.x * 256 + threadIdx.x;
    if ((size_t)idx * 4 >= (size_t)MM * CC) return;
    const float4 v = ((const float4*)x)[idx];
    __nv_bfloat162 h01, h23, l01, l23;
    h01.x = __float2bfloat16(v.x); h01.y = __float2bfloat16(v.y);
    h23.x = __float2bfloat16(v.z); h23.y = __float2bfloat16(v.w);
    l01.x = __float2bfloat16(v.x - __bfloat162float(h01.x));
    l01.y = __float2bfloat16(v.y - __bfloat162float(h01.y));
    l23.x = __float2bfloat16(v.z - __bfloat162float(h23.x));
    l23.y = __float2bfloat16(v.w - __bfloat162float(h23.y));
    ((__nv_bfloat162*)g_xhi)[idx * 2]     = h01;
    ((__nv_bfloat162*)g_xhi)[idx * 2 + 1] = h23;
    ((__nv_bfloat162*)g_xlo)[idx * 2]     = l01;
    ((__nv_bfloat162*)g_xlo)[idx * 2 + 1] = l23;
}

__global__ __launch_bounds__(256)
void transpose_split_kernel(const float* __restrict__ W,
                            __nv_bfloat16* __restrict__ Thi,
                            __nv_bfloat16* __restrict__ Tlo, int N)
{
    __shared__ float tile[32][33];
    const int tx = threadIdx.x, ty = threadIdx.y;            // 32 x 8
    const int nbase = blockIdx.x * 32, kbase = blockIdx.y * 32;
#pragma unroll
    for (int i = 0; i < 4; i++)
        tile[ty + i * 8][tx] = W[(size_t)(kbase + ty + i * 8) * N + nbase + tx];
    __syncthreads();
#pragma unroll
    for (int i = 0; i < 4; i++) {
        const int n = nbase + ty + i * 8;
        const int k = kbase + tx;
        const float v = tile[tx][ty + i * 8];
        const __nv_bfloat16 h = __float2bfloat16(v);
        Thi[(size_t)n * CC + k] = h;
        Tlo[(size_t)n * CC + k] = __float2bfloat16(v - __bfloat162float(h));
    }
}

// ---------------- mma.sync bf16x3 GEMM (validated R12) ---------------------
// EPI==0: bias (+q scale 1/8) + split + scatter to g_{q,k,v}{hi,lo}.
// EPI==1: out + bias (fp32).
#define SROW 72
template<int EPI>
__global__ __launch_bounds__(256)
void gemm_mma_bf16x3(const __nv_bfloat16* __restrict__ Ahi, const __nv_bfloat16* __restrict__ Alo,
                     const __nv_bfloat16* __restrict__ Bhi, const __nv_bfloat16* __restrict__ Blo,
                     const float* __restrict__ bias, float* __restrict__ out)
{
    extern __shared__ __nv_bfloat16 smem[];   // 384 rows x 72 halves
    const uint32_t sb = smem_u32(smem);
    const int tid = threadIdx.x;
    const int lane = tid & 31, w = tid >> 5;
    const int wm = w & 3, wn = w >> 2;
    const int bn = blockIdx.x, bm = blockIdx.y;

    const int q4   = lane >> 3;
    const int rowA = (lane & 7) + (q4 & 1) * 8;
    const int kA   = (q4 >> 1) * 8;
    const int rowB = (lane & 7) + ((lane >> 4) & 1) * 8;
    const int kB   = ((lane >> 3) & 1) * 8;

    uint32_t aH[2], aL[2], bH[2], bL[2];
#pragma unroll
    for (int mt = 0; mt < 2; ++mt) {
        const int r = wm * 32 + mt * 16 + rowA;
        aH[mt] = sb + 2u * (r * SROW + kA);
        aL[mt] = aH[mt] + 2u * 128 * SROW;
    }
#pragma unroll
    for (int p = 0; p < 2; ++p) {
        const int r = 256 + wn * 32 + p * 16 + rowB;
        bH[p] = sb + 2u * (r * SROW + kB);
        bL[p] = bH[p] + 2u * 64 * SROW;
    }

    float acc[2][4][4];
#pragma unroll
    for (int mt = 0; mt < 2; ++mt)
#pragma unroll
        for (int nt = 0; nt < 4; ++nt)
#pragma unroll
            for (int e = 0; e < 4; ++e) acc[mt][nt][e] = 0.f;

#pragma unroll 1
    for (int ck = 0; ck < 16; ++ck) {
#pragma unroll
        for (int i = 0; i < 12; ++i) {
            const int idx = tid + 256 * i;
            const int r = idx >> 3, cg = idx & 7;
            const __nv_bfloat16* src;
            int grow;
            if (r < 128)      { src = Ahi; grow = bm * 128 + r; }
            else if (r < 256) { src = Alo; grow = bm * 128 + (r - 128); }
            else if (r < 320) { src = Bhi; grow = bn * 64 + (r - 256); }
            else              { src = Blo; grow = bn * 64 + (r - 320); }
            const uint4 v = *(const uint4*)(src + (size_t)grow * CC + ck * 64 + cg * 8);
            *(uint4*)((char*)smem + ((size_t)r * SROW + cg * 8) * 2) = v;
        }
        __syncthreads();

#pragma unroll
        for (int ks = 0; ks < 4; ++ks) {
            const uint32_t koff = ks * 32;
            uint32_t ah[2][4], al[2][4], bh[2][4], bl[2][4];
#pragma unroll
            for (int mt = 0; mt < 2; ++mt) {
                LDSM4(ah[mt][0], ah[mt][1], ah[mt][2], ah[mt][3], aH[mt] + koff);
                LDSM4(al[mt][0], al[mt][1], al[mt][2], al[mt][3], aL[mt] + koff);
            }
#pragma unroll
            for (int p = 0; p < 2; ++p) {
                LDSM4(bh[p][0], bh[p][1], bh[p][2], bh[p][3], bH[p] + koff);
                LDSM4(bl[p][0], bl[p][1], bl[p][2], bl[p][3], bL[p] + koff);
            }
#pragma unroll
            for (int mt = 0; mt < 2; ++mt)
#pragma unroll
                for (int p = 0; p < 2; ++p)
#pragma unroll
                    for (int t = 0; t < 2; ++t) {
                        const int nt = p * 2 + t;
                        MMA16816(acc[mt][nt], ah[mt][0], ah[mt][1], ah[mt][2], ah[mt][3],
                                 bh[p][t * 2], bh[p][t * 2 + 1]);
                        MMA16816(acc[mt][nt], ah[mt][0], ah[mt][1], ah[mt][2], ah[mt][3],
                                 bl[p][t * 2], bl[p][t * 2 + 1]);
                        MMA16816(acc[mt][nt], al[mt][0], al[mt][1], al[mt][2], al[mt][3],
                                 bh[p][t * 2], bh[p][t * 2 + 1]);
                    }
        }
        __syncthreads();
    }

    const int g = lane >> 2, tg = lane & 3;
#pragma unroll
    for (int mt = 0; mt < 2; ++mt)
#pragma unroll
        for (int nt = 0; nt < 4; ++nt) {
            const int col = bn * 64 + wn * 32 + nt * 8 + tg * 2;
            const float bi0 = bias[col], bi1 = bias[col + 1];
#pragma unroll
            for (int half = 0; half < 2; ++half) {
                const int row = bm * 128 + wm * 32 + mt * 16 + g + half * 8;
                float v0 = acc[mt][nt][half * 2]     + bi0;
                float v1 = acc[mt][nt][half * 2 + 1] + bi1;
                if (EPI == 0) {
                    const int b = row >> 11, tt = row & (TT - 1);
                    const int sel = col >> 10;
                    const int c = col & (CC - 1);
                    const int h = c >> 6, d = c & 63;
                    if (sel == 0) { v0 *= 0.125f; v1 *= 0.125f; }   // fold 1/sqrt(D)
                    __nv_bfloat16* dh = (sel == 0) ? g_qhi : (sel == 1) ? g_khi : g_vhi;
                    __nv_bfloat16* dl = (sel == 0) ? g_qlo : (sel == 1) ? g_klo : g_vlo;
                    uint32_t hi, lo;
                    split2(v0, v1, hi, lo);
                    const size_t o2 = ((size_t)(b * HH + h) * TT + tt) * DD + d;
                    *(uint32_t*)(dh + o2) = hi;
                    *(uint32_t*)(dl + o2) = lo;
                } else {
                    float2* p2 = (float2*)&out[(size_t)row * CC + col];
                    *p2 = make_float2(v0, v1);
                }
            }
        }
}

// ---------------- FA2-style mma.sync attention (bf16x3) --------------------
// Block: 128 q-rows x (head, batch); 8 warps each own 16 rows.
// KV tiles of 64. smem: 256 rows x SROW halves (36864 B, static).
__global__ __launch_bounds__(256)
void attn_mma_kernel()
{
    __shared__ __nv_bfloat16 sm[256 * SROW];
    const uint32_t sb = smem_u32(sm);
    const int tid = threadIdx.x, lane = tid & 31, w = tid >> 5;
    const int qt = blockIdx.x, h = blockIdx.y, b = blockIdx.z;
    const int qrow0 = qt * 128;
    const size_t base = (size_t)(b * HH + h) * TT * DD;

    const int q4   = lane >> 3;
    const int rowA = (lane & 7) + (q4 & 1) * 8;
    const int kA   = (q4 >> 1) * 8;
    const int rowB = (lane & 7) + ((lane >> 4) & 1) * 8;
    const int kB   = ((lane >> 3) & 1) * 8;
    const int g = lane >> 2, tg = lane & 3;

    // ---- stage Q hi/lo (rows 0-127 hi, 128-255 lo), then frag to regs ----
#pragma unroll
    for (int i = 0; i < 8; ++i) {
        const int idx = tid + 256 * i;                 // 0..2047
        const int r = (idx >> 3) & 127, cg = idx & 7;
        const __nv_bfloat16* src = (idx < 1024) ? g_qhi : g_qlo;
        const int srow = ((idx < 1024) ? 0 : 128) + r;
        const uint4 v = *(const uint4*)(src + base + (size_t)(qrow0 + r) * DD + cg * 8);
        *(uint4*)((char*)sm + ((size_t)srow * SROW + cg * 8) * 2) = v;
    }
    __syncthreads();

    uint32_t qh[4][4], ql[4][4];
#pragma unroll
    for (int ks = 0; ks < 4; ++ks) {
        const uint32_t a = sb + 2u * ((w * 16 + rowA) * SROW + ks * 16 + kA);
        LDSM4(qh[ks][0], qh[ks][1], qh[ks][2], qh[ks][3], a);
        LDSM4(ql[ks][0], ql[ks][1], ql[ks][2], ql[ks][3], a + 2u * 128 * SROW);
    }
    __syncthreads();

    float o[8][4];
#pragma unroll
    for (int dt = 0; dt < 8; ++dt)
#pragma unroll
        for (int e = 0; e < 4; ++e) o[dt][e] = 0.f;
    float mrow[2] = {-1e30f, -1e30f}, lrow[2] = {0.f, 0.f};

    const int wr0 = qrow0 + w * 16;
    const int nkv = 2 * (qt + 1);

#pragma unroll 1
    for (int kt = 0; kt < nkv; ++kt) {
        const int kvbase = kt * 64;
        // ---- load K hi(0-63), K lo(64-127), V hi(128-191), V lo(192-255) ----
#pragma unroll
        for (int i = 0; i < 8; ++i) {
            const int idx = tid + 256 * i;             // 0..2047
            const int a = idx >> 9;                    // 0..3
            const int r = (idx >> 3) & 63, cg = idx & 7;
            const __nv_bfloat16* src = (a == 0) ? g_khi : (a == 1) ? g_klo
                                     : (a == 2) ? g_vhi : g_vlo;
            const uint4 v = *(const uint4*)(src + base + (size_t)(kvbase + r) * DD + cg * 8);
            *(uint4*)((char*)sm + ((size_t)(a * 64 + r) * SROW + cg * 8) * 2) = v;
        }
        __syncthreads();

        // ---- S = Q K^T (hi*hi + hi*lo + lo*hi) ----
        float s[8][4];
#pragma unroll
        for (int nt = 0; nt < 8; ++nt)
#pragma unroll
            for (int e = 0; e < 4; ++e) s[nt][e] = 0.f;

#pragma unroll
        for (int ks = 0; ks < 4; ++ks)
#pragma unroll
            for (int p = 0; p < 4; ++p) {
                const uint32_t ka = sb + 2u * ((p * 16 + rowB) * SROW + ks * 16 + kB);
                uint32_t kh0, kh1, kh2, kh3, kl0, kl1, kl2, kl3;
                LDSM4(kh0, kh1, kh2, kh3, ka);
                LDSM4(kl0, kl1, kl2, kl3, ka + 2u * 64 * SROW);
                MMA16816(s[2*p],   qh[ks][0], qh[ks][1], qh[ks][2], qh[ks][3], kh0, kh1);
                MMA16816(s[2*p],   qh[ks][0], qh[ks][1], qh[ks][2], qh[ks][3], kl0, kl1);
                MMA16816(s[2*p],   ql[ks][0], ql[ks][1], ql[ks][2], ql[ks][3], kh0, kh1);
                MMA16816(s[2*p+1], qh[ks][0], qh[ks][1], qh[ks][2], qh[ks][3], kh2, kh3);
                MMA16816(s[2*p+1], qh[ks][0], qh[ks][1], qh[ks][2], qh[ks][3], kl2, kl3);
                MMA16816(s[2*p+1], ql[ks][0], ql[ks][1], ql[ks][2], ql[ks][3], kh2, kh3);
            }

        // ---- causal mask (diag region only) ----
        if (kvbase + 63 > wr0) {
#pragma unroll
            for (int nt = 0; nt < 8; ++nt)
#pragma unroll
                for (int e = 0; e < 4; ++e) {
                    const int col = kvbase + nt * 8 + tg * 2 + (e & 1);
                    const int row = wr0 + g + (e >> 1) * 8;
                    if (col > row) s[nt][e] = -1e30f;
                }
        }

        // ---- online softmax (rows g, g+8; reduce across quad lanes) ----
#pragma unroll
        for (int i = 0; i < 2; ++i) {
            float rm = -1e30f;
#pragma unroll
            for (int nt = 0; nt < 8; ++nt)
                rm = fmaxf(rm, fmaxf(s[nt][i*2], s[nt][i*2+1]));
            rm = fmaxf(rm, __shfl_xor_sync(0xffffffffu, rm, 1));
            rm = fmaxf(rm, __shfl_xor_sync(0xffffffffu, rm, 2));
            const float mn = fmaxf(mrow[i], rm);
            const float corr = __expf(mrow[i] - mn);
            mrow[i] = mn;
            float rs = 0.f;
#pragma unroll
            for (int nt = 0; nt < 8; ++nt) {
                const float p0 = __expf(s[nt][i*2] - mn);
                const float p1 = __expf(s[nt][i*2+1] - mn);
                s[nt][i*2] = p0; s[nt][i*2+1] = p1;
                rs += p0 + p1;
            }
            rs += __shfl_xor_sync(0xffffffffu, rs, 1);
            rs += __shfl_xor_sync(0xffffffffu, rs, 2);
            lrow[i] = lrow[i] * corr + rs;
#pragma unroll
            for (int dt = 0; dt < 8; ++dt) {
                o[dt][i*2]   *= corr;
                o[dt][i*2+1] *= corr;
            }
        }

        // ---- O += P V (P split hi/lo as A frags; V via ldmatrix.trans) ----
#pragma unroll
        for (int p = 0; p < 4; ++p) {
            uint32_t ph[4], pl[4];
            split2(s[2*p][0],   s[2*p][1],   ph[0], pl[0]);
            split2(s[2*p][2],   s[2*p][3],   ph[1], pl[1]);
            split2(s[2*p+1][0], s[2*p+1][1], ph[2], pl[2]);
            split2(s[2*p+1][2], s[2*p+1][3], ph[3], pl[3]);

            const int vrow = (lane & 7) + ((lane >> 3) & 1) * 8;
            const int vcolb = (lane >> 4) * 8;
#pragma unroll
            for (int dt2 = 0; dt2 < 4; ++dt2) {
                const uint32_t va = sb + 2u * ((128 + p * 16 + vrow) * SROW + dt2 * 16 + vcolb);
                uint32_t vh0, vh1, vh2, vh3, vl0, vl1, vl2, vl3;
                LDSM4T(vh0, vh1, vh2, vh3, va);
                LDSM4T(vl0, vl1, vl2, vl3, va + 2u * 64 * SROW);
                MMA16816(o[dt2*2],   ph[0], ph[1], ph[2], ph[3], vh0, vh1);
                MMA16816(o[dt2*2],   pl[0], pl[1], pl[2], pl[3], vh0, vh1);
                MMA16816(o[dt2*2],   ph[0], ph[1], ph[2], ph[3], vl0, vl1);
                MMA16816(o[dt2*2+1], ph[0], ph[1], ph[2], ph[3], vh2, vh3);
                MMA16816(o[dt2*2+1], pl[0], pl[1], pl[2], pl[3], vh2, vh3);
                MMA16816(o[dt2*2+1], ph[0], ph[1], ph[2], ph[3], vl2, vl3);
            }
        }
        __syncthreads();
    }

    // ---- epilogue: normalize, split, write y hi/lo ----
    const float inv0 = 1.f / lrow[0], inv1 = 1.f / lrow[1];
    const int r0 = qrow0 + w * 16 + g, r1 = r0 + 8;
#pragma unroll
    for (int dt = 0; dt < 8; ++dt) {
        const int col = h * DD + dt * 8 + tg * 2;
        uint32_t hi, lo;
        split2(o[dt][0] * inv0, o[dt][1] * inv0, hi, lo);
        *(uint32_t*)(g_yhi + (size_t)(b * TT + r0) * CC + col) = hi;
        *(uint32_t*)(g_ylo + (size_t)(b * TT + r0) * CC + col) = lo;
        split2(o[dt][2] * inv1, o[dt][3] * inv1, hi, lo);
        *(uint32_t*)(g_yhi + (size_t)(b * TT + r1) * CC + col) = hi;
        *(uint32_t*)(g_ylo + (size_t)(b * TT + r1) * CC + col) = lo;
    }
}

// ---------------------------------------------------------------------------
extern "C" void kernel_launch(void* const* d_in, const int* in_sizes, int n_in,
                              void* d_out, int out_size)
{
    const float* x      = (const float*)d_in[0];
    const float* w_attn = (const float*)d_in[1];
    const float* b_attn = (const float*)d_in[2];
    const float* w_proj = (const float*)d_in[3];
    const float* b_proj = (const float*)d_in[4];
    float* out = (float*)d_out;

    const int gemm_smem = 384 * SROW * 2;                     // 55296 B
    cudaFuncSetAttribute(gemm_mma_bf16x3<0>, cudaFuncAttributeMaxDynamicSharedMemorySize, gemm_smem);
    cudaFuncSetAttribute(gemm_mma_bf16x3<1>, cudaFuncAttributeMaxDynamicSharedMemorySize, gemm_smem);

    __nv_bfloat16 *xhi, *xlo, *wahi, *walo, *wphi, *wplo, *yhi, *ylo;
    cudaGetSymbolAddress((void**)&xhi,  g_xhi);
    cudaGetSymbolAddress((void**)&xlo,  g_xlo);
    cudaGetSymbolAddress((void**)&wahi, g_wahi);
    cudaGetSymbolAddress((void**)&walo, g_walo);
    cudaGetSymbolAddress((void**)&wphi, g_wphi);
    cudaGetSymbolAddress((void**)&wplo, g_wplo);
    cudaGetSymbolAddress((void**)&yhi,  g_yhi);
    cudaGetSymbolAddress((void**)&ylo,  g_ylo);

    // prep: split X, transpose+split weights
    split_x_kernel<<<(MM * CC / 4 + 255) / 256, 256>>>(x);
    transpose_split_kernel<<<dim3(NQKV / 32, CC / 32), dim3(32, 8)>>>(w_attn, wahi, walo, NQKV);
    transpose_split_kernel<<<dim3(CC / 32, CC / 32),   dim3(32, 8)>>>(w_proj, wphi, wplo, CC);

    // QKV = X @ W_attn + b -> q/k/v hi/lo bf16 (q pre-scaled 1/8)
    gemm_mma_bf16x3<0><<<dim3(NQKV / 64, MM / 128), 256, gemm_smem>>>(xhi, xlo, wahi, walo, b_attn, nullptr);

    // attention (mma.sync bf16x3 flash) -> y hi/lo
    attn_mma_kernel<<<dim3(TT / 128, HH, BB), 256>>>();

    // out = y @ W_proj + b
    gemm_mma_bf16x3<1><<<dim3(CC / 64, MM / 128), 256, gemm_smem>>>(yhi, ylo, wphi, wplo, b_proj, out);
}